// round 3
// baseline (speedup 1.0000x reference)
#include <cuda_runtime.h>
#include <mma.h>
#include <cstdint>

using namespace nvcuda;

#define NN 50000
#define NE 312500
#define WD 256
#define MROWS 50048          // 391 * 128, padded rows so GEMM tiles store unguarded
#define NCHUNK 49            // ceil(50000/1024)

// ---- scratch (device globals; no allocation allowed) ----
__device__ int   g_deg[NN];
__device__ int   g_cursor[NN];
__device__ float g_dinv[NN];
__device__ int   g_off[NN + 1];
__device__ int   g_srcs[NE];
__device__ float g_h[MROWS * WD];     // h = x @ W^T (unscaled), 51.2 MB — L2-resident
__device__ int   g_csum[NCHUNK];
__device__ int   g_coff[NCHUNK];
__device__ int   g_is64;

// ---------------------------------------------------------------------------
// index dtype detection: reference asks for int64, but JAX without x64 gives
// int32. Reading int32 pairs as int64 yields values >= 2^32 whenever the high
// word (a random index in [0,50000)) is nonzero, so 64 in-range int64 reads
// conclusively mean the buffer really is int64.
// ---------------------------------------------------------------------------
__global__ void k_detect(const void* __restrict__ ei) {
    const long long* p = (const long long*)ei;
    int ok = 1;
    for (int i = 0; i < 64; i++) {
        long long v = p[i];
        if (v < 0 || v >= NN) ok = 0;
    }
    g_is64 = ok;
}

__device__ __forceinline__ int get_idx(const void* __restrict__ ei, int pos) {
    if (g_is64) return (int)((const long long*)ei)[pos];
    return ((const int*)ei)[pos];
}

// ---------------------------------------------------------------------------
// CSR build
// ---------------------------------------------------------------------------
__global__ void k_init() {
    int i = blockIdx.x * blockDim.x + threadIdx.x;
    if (i < NN) { g_deg[i] = 1; g_cursor[i] = 0; }   // deg starts at 1 (self loop)
}

__global__ void k_count(const void* __restrict__ ei) {
    int e = blockIdx.x * blockDim.x + threadIdx.x;
    if (e < NE) {
        int dst = get_idx(ei, NE + e);
        atomicAdd(&g_deg[dst], 1);
    }
}

__global__ void k_scan_a() {   // per-1024-chunk edge-count sums
    int base = blockIdx.x * 1024;
    int s = 0;
    for (int j = threadIdx.x; j < 1024; j += 256) {
        int i = base + j;
        if (i < NN) s += g_deg[i] - 1;
    }
    #pragma unroll
    for (int m = 16; m; m >>= 1) s += __shfl_xor_sync(0xffffffffu, s, m);
    __shared__ int wsum[8];
    if ((threadIdx.x & 31) == 0) wsum[threadIdx.x >> 5] = s;
    __syncthreads();
    if (threadIdx.x == 0) {
        int t = 0;
        #pragma unroll
        for (int w = 0; w < 8; w++) t += wsum[w];
        g_csum[blockIdx.x] = t;
    }
}

__global__ void k_scan_b() {   // serial scan of 49 partials (1 thread, trivial)
    int run = 0;
    for (int b = 0; b < NCHUNK; b++) { g_coff[b] = run; run += g_csum[b]; }
    g_off[NN] = run;
}

__global__ void k_scan_c() {   // intra-chunk exclusive scan + dinv
    __shared__ int sm[1024];
    int i = blockIdx.x * 1024 + threadIdx.x;
    int v = (i < NN) ? g_deg[i] - 1 : 0;
    sm[threadIdx.x] = v;
    __syncthreads();
    for (int off = 1; off < 1024; off <<= 1) {
        int t = (threadIdx.x >= off) ? sm[threadIdx.x - off] : 0;
        __syncthreads();
        sm[threadIdx.x] += t;
        __syncthreads();
    }
    if (i < NN) {
        g_off[i]  = g_coff[blockIdx.x] + sm[threadIdx.x] - v;   // exclusive
        g_dinv[i] = rsqrtf((float)g_deg[i]);
    }
}

__global__ void k_fill(const void* __restrict__ ei) {
    int e = blockIdx.x * blockDim.x + threadIdx.x;
    if (e < NE) {
        int src = get_idx(ei, e);
        int dst = get_idx(ei, NE + e);
        int p = atomicAdd(&g_cursor[dst], 1);
        g_srcs[g_off[dst] + p] = src;
    }
}

// ---------------------------------------------------------------------------
// GEMM: g_h = x @ W^T via tf32 wmma (m16n16k8). Block tile 128x128, 8 warps,
// warp tile 32x64 (2x4 acc frags). K staged through smem in 32-chunks.
// ---------------------------------------------------------------------------
#define SLD 40   // smem leading dim (pad to kill bank conflicts; mult of 4 elems)

__global__ __launch_bounds__(256) void k_gemm(const float* __restrict__ x,
                                              const float* __restrict__ Wm) {
    __shared__ float xs[128 * SLD];
    __shared__ float ws[128 * SLD];
    int tid = threadIdx.x;
    int r0 = blockIdx.x * 128;
    int n0 = blockIdx.y * 128;
    int w  = tid >> 5;
    int wm = w & 3;        // 4 warps along M (32 rows each)
    int wn = w >> 2;       // 2 warps along N (64 cols each)

    wmma::fragment<wmma::accumulator, 16, 16, 8, float> c[2][4];
    #pragma unroll
    for (int i = 0; i < 2; i++)
        #pragma unroll
        for (int j = 0; j < 4; j++) wmma::fill_fragment(c[i][j], 0.0f);

    const float4* xg = (const float4*)x;
    const float4* wg = (const float4*)Wm;

    for (int kc = 0; kc < WD; kc += 32) {
        #pragma unroll
        for (int it = 0; it < 4; it++) {
            int t = it * 256 + tid;
            int row = t >> 3, kq = t & 7;               // 32 cols = 8 float4
            float4 v = make_float4(0.f, 0.f, 0.f, 0.f);
            int gr = r0 + row;
            if (gr < NN) v = xg[gr * 64 + (kc >> 2) + kq];
            *(float4*)(xs + row * SLD + kq * 4) = v;
            float4 u = wg[(n0 + row) * 64 + (kc >> 2) + kq];
            *(float4*)(ws + row * SLD + kq * 4) = u;
        }
        __syncthreads();
        #pragma unroll
        for (int kk = 0; kk < 32; kk += 8) {
            wmma::fragment<wmma::matrix_a, 16, 16, 8, wmma::precision::tf32, wmma::row_major> a[2];
            wmma::fragment<wmma::matrix_b, 16, 16, 8, wmma::precision::tf32, wmma::col_major> bf[4];
            #pragma unroll
            for (int i = 0; i < 2; i++) {
                wmma::load_matrix_sync(a[i], xs + (wm * 32 + i * 16) * SLD + kk, SLD);
                #pragma unroll
                for (int e2 = 0; e2 < a[i].num_elements; e2++)
                    a[i].x[e2] = wmma::__float_to_tf32(a[i].x[e2]);
            }
            #pragma unroll
            for (int j = 0; j < 4; j++) {
                // B[k][n] = W[n][k]: col_major over ws[n][k]
                wmma::load_matrix_sync(bf[j], ws + (wn * 64 + j * 16) * SLD + kk, SLD);
                #pragma unroll
                for (int e2 = 0; e2 < bf[j].num_elements; e2++)
                    bf[j].x[e2] = wmma::__float_to_tf32(bf[j].x[e2]);
            }
            #pragma unroll
            for (int i = 0; i < 2; i++)
                #pragma unroll
                for (int j = 0; j < 4; j++)
                    wmma::mma_sync(c[i][j], a[i], bf[j], c[i][j]);
        }
        __syncthreads();
    }
    #pragma unroll
    for (int i = 0; i < 2; i++)
        #pragma unroll
        for (int j = 0; j < 4; j++) {
            float* dst = g_h + (r0 + wm * 32 + i * 16) * WD + n0 + wn * 64 + j * 16;
            wmma::store_matrix_sync(dst, c[i][j], WD, wmma::mem_row_major);  // rows < MROWS, safe
        }
}

// ---------------------------------------------------------------------------
// Gather + bias + LayerNorm + ReLU. blockDim (64,4): 64 threads x float4 per
// node row; 4 nodes per block. NN % 4 == 0 so no ragged groups.
// out[d] = relu( LN( dinv[d]*(sum_e dinv[s]*h[s] + dinv[d]*h[d]) + b ) )
// ---------------------------------------------------------------------------
__global__ __launch_bounds__(256) void k_agg(const float* __restrict__ bias,
                                             const float* __restrict__ gamma,
                                             const float* __restrict__ beta,
                                             float* __restrict__ out) {
    int tx = threadIdx.x, ty = threadIdx.y;
    int node = blockIdx.x * 4 + ty;
    const float4* h4 = (const float4*)g_h;

    float di = g_dinv[node];
    float4 s = h4[node * 64 + tx];
    float4 acc = make_float4(di * s.x, di * s.y, di * s.z, di * s.w);

    int e0 = g_off[node], e1 = g_off[node + 1];
    for (int e = e0; e < e1; e++) {
        int sn = g_srcs[e];
        float ds = g_dinv[sn];
        float4 v = h4[sn * 64 + tx];
        acc.x = fmaf(ds, v.x, acc.x);
        acc.y = fmaf(ds, v.y, acc.y);
        acc.z = fmaf(ds, v.z, acc.z);
        acc.w = fmaf(ds, v.w, acc.w);
    }

    const float4* b4 = (const float4*)bias;
    float4 bb = b4[tx];
    float4 pre;
    pre.x = fmaf(di, acc.x, bb.x);
    pre.y = fmaf(di, acc.y, bb.y);
    pre.z = fmaf(di, acc.z, bb.z);
    pre.w = fmaf(di, acc.w, bb.w);

    float s1 = pre.x + pre.y + pre.z + pre.w;
    float s2 = pre.x * pre.x + pre.y * pre.y + pre.z * pre.z + pre.w * pre.w;
    #pragma unroll
    for (int m = 16; m; m >>= 1) {
        s1 += __shfl_xor_sync(0xffffffffu, s1, m);
        s2 += __shfl_xor_sync(0xffffffffu, s2, m);
    }
    __shared__ float2 part[4][2];
    if ((tx & 31) == 0) part[ty][tx >> 5] = make_float2(s1, s2);
    __syncthreads();
    float S  = part[ty][0].x + part[ty][1].x;
    float SS = part[ty][0].y + part[ty][1].y;
    float mean = S * (1.0f / 256.0f);
    float var  = SS * (1.0f / 256.0f) - mean * mean;
    float rstd = rsqrtf(var + 1e-5f);

    const float4* g4  = (const float4*)gamma;
    const float4* be4 = (const float4*)beta;
    float4 gg = g4[tx], bt = be4[tx];
    float4 o;
    o.x = fmaxf(0.f, fmaf((pre.x - mean) * rstd, gg.x, bt.x));
    o.y = fmaxf(0.f, fmaf((pre.y - mean) * rstd, gg.y, bt.y));
    o.z = fmaxf(0.f, fmaf((pre.z - mean) * rstd, gg.z, bt.z));
    o.w = fmaxf(0.f, fmaf((pre.w - mean) * rstd, gg.w, bt.w));
    ((float4*)out)[node * 64 + tx] = o;
}

// ---------------------------------------------------------------------------
extern "C" void kernel_launch(void* const* d_in, const int* in_sizes, int n_in,
                              void* d_out, int out_size) {
    const float* x     = (const float*)d_in[0];
    const void*  ei    = d_in[1];                 // int64 or int32, detected on device
    const float* Wm    = (const float*)d_in[2];
    const float* bias  = (const float*)d_in[3];
    const float* gamma = (const float*)d_in[4];
    const float* beta  = (const float*)d_in[5];
    float* out = (float*)d_out;

    k_detect<<<1, 1>>>(ei);
    k_init<<<(NN + 255) / 256, 256>>>();
    k_count<<<(NE + 255) / 256, 256>>>(ei);
    k_scan_a<<<NCHUNK, 256>>>();
    k_scan_b<<<1, 1>>>();
    k_scan_c<<<NCHUNK, 1024>>>();
    k_fill<<<(NE + 255) / 256, 256>>>(ei);
    k_gemm<<<dim3(391, 2), 256>>>(x, Wm);
    k_agg<<<NN / 4, dim3(64, 4)>>>(bias, gamma, beta, out);
}